// round 8
// baseline (speedup 1.0000x reference)
#include <cuda_runtime.h>
#include <math.h>

#define G_   4
#define HW   4096
#define N_   32
#define TH   32          // tile height
#define TW   16          // tile width
#define HALO 3
#define SH   (TH + 2*HALO)   // 38
#define SW   (TW + 2*HALO)   // 22
#define PSTR 20              // floats per pixel in smem (pad 16->20: conflict-free)
#define THREADS 128
#define PPT  4

// dynamic smem carve (bytes)
#define SWC_U64   (9*16*12)          // [pos][c][slot12]: k0-4 @0-4, k5-8 @6-9
#define SWE_U64   (9*16*8)           // [k][c][op-pair]
#define SB_U64    10
#define TILE_OFF  ((SWC_U64 + SWE_U64 + SB_U64) * 8)        // 23120 B
#define SMEM_BYTES (TILE_OFF + SH*SW*PSTR*4)                // +66880 = 90000 B

typedef unsigned long long u64;

__device__ float g_pre [N_*64*HW];
__device__ float g_part[N_*4*8*32];
__device__ float g_stat[2*N_*64];    // [0]=mean, [1]=inv per (n,oc)
__device__ float g_touch[32];

// ---- packed f32x2 helpers ----
__device__ __forceinline__ u64 pack2(float lo, float hi) {
    u64 r; asm("mov.b64 %0,{%1,%2};" : "=l"(r) : "f"(lo), "f"(hi)); return r;
}
__device__ __forceinline__ float2 unpack2(u64 v) {
    float2 r; asm("mov.b64 {%0,%1},%2;" : "=f"(r.x), "=f"(r.y) : "l"(v)); return r;
}
__device__ __forceinline__ void ffma2(u64 &d, u64 a, u64 b) {
    asm("fma.rn.f32x2 %0,%1,%2,%0;" : "+l"(d) : "l"(a), "l"(b));
}
__device__ __forceinline__ u64 mul2(u64 a, u64 b) {
    u64 r; asm("mul.rn.f32x2 %0,%1,%2;" : "=l"(r) : "l"(a), "l"(b)); return r;
}
__device__ __forceinline__ u64 dup2(float v) { return pack2(v, v); }

// Slot-0 dummy: makes launch count per call = 4 so ncu's -s 5 -c 1 lands on
// fused_kernel (global launch idx 5 = slot 1 of replay 1). Deterministic.
__global__ void touch_kernel() { g_touch[threadIdx.x] = 1.0f; }

// One k-chunk: offset conv for taps [KLO,KLO+S) reading smem tile (adjacent-row
// pixel blocking with shared tap loads), then deformable sampling + einsum.
template<int KLO, int S>
__device__ __forceinline__ void chunk(
    u64 acc[PPT][8], const float* __restrict__ tile, const float* __restrict__ xg,
    const u64* __restrict__ swc, const u64* __restrict__ swe,
    const u64* __restrict__ sb,
    int r0loc, int lanex, int ty0, int tx0)
{
    // ---- Phase A: conv accumulation; 4 adjacent pixel rows share tap loads ----
    u64 ao[PPT][S];
    #pragma unroll
    for (int pix = 0; pix < PPT; pix++)
        #pragma unroll
        for (int kk = 0; kk < S; kk++) ao[pix][kk] = sb[KLO + kk];

    #pragma unroll 1
    for (int j = 0; j < 4; j++) {
        #pragma unroll
        for (int cx = 0; cx < 3; cx++) {
            // 6 tap rows cover the 3x3 windows of 4 adjacent pixel rows
            float4 R[6];
            #pragma unroll
            for (int ry = 0; ry < 6; ry++)
                R[ry] = *reinterpret_cast<const float4*>(
                    tile + ((r0loc + HALO - 1 + ry) * SW + (lanex + HALO - 1 + cx)) * PSTR + 4*j);
            #pragma unroll
            for (int posr = 0; posr < 3; posr++) {
                const int pos = posr * 3 + cx;
                #pragma unroll
                for (int q = 0; q < 4; q++) {
                    const u64* wb = swc + (pos * 16 + 4*j + q) * 12;
                    u64 wr[S];
                    if (S == 5) {
                        const ulonglong2 a = *reinterpret_cast<const ulonglong2*>(wb);
                        const ulonglong2 b = *reinterpret_cast<const ulonglong2*>(wb + 2);
                        wr[0] = a.x; wr[1] = a.y; wr[2] = b.x; wr[3] = b.y; wr[4] = wb[4];
                    } else {
                        const ulonglong2 a = *reinterpret_cast<const ulonglong2*>(wb + 6);
                        const ulonglong2 b = *reinterpret_cast<const ulonglong2*>(wb + 8);
                        wr[0] = a.x; wr[1] = a.y; wr[2] = b.x; wr[3] = b.y;
                    }
                    #pragma unroll
                    for (int pix = 0; pix < PPT; pix++) {
                        const float4 X = R[pix + posr];
                        const float xv = (q == 0) ? X.x : (q == 1) ? X.y
                                       : (q == 2) ? X.z : X.w;
                        const u64 xd = dup2(xv);
                        #pragma unroll
                        for (int kk = 0; kk < S; kk++) ffma2(ao[pix][kk], wr[kk], xd);
                    }
                }
            }
        }
    }

    // ---- Phase B: sampling (smem, with rare global fallback) + einsum ----
    const int oy = ty0 - HALO, ox = tx0 - HALO;
    #pragma unroll 1
    for (int kk = 0; kk < S; kk++) {
        const int k = KLO + kk;
        const int kdy = k / 3 - 1, kdx = k % 3 - 1;
        u64 wwd[PPT][4];
        int cw[PPT][4];
        bool inw[PPT];
        #pragma unroll
        for (int pix = 0; pix < PPT; pix++) {
            const float2 off = unpack2(ao[pix][kk]);
            const int hg = ty0 + r0loc + pix;
            const int wg = tx0 + lanex;
            const float py = (float)(hg + kdy) + off.x;
            const float px = (float)(wg + kdx) + off.y;
            const float y0f = floorf(py), x0f = floorf(px);
            const float fy = py - y0f, fx = px - x0f;
            const int y0 = (int)y0f, x0 = (int)x0f;
            const bool vy0 = (y0 >= 0)  && (y0 < 64);
            const bool vy1 = (y0 >= -1) && (y0 < 63);
            const bool vx0 = (x0 >= 0)  && (x0 < 64);
            const bool vx1 = (x0 >= -1) && (x0 < 63);
            wwd[pix][0] = dup2((1.f - fy) * (1.f - fx) * ((vy0 && vx0) ? 1.f : 0.f));
            wwd[pix][1] = dup2((1.f - fy) * fx         * ((vy0 && vx1) ? 1.f : 0.f));
            wwd[pix][2] = dup2(fy * (1.f - fx)         * ((vy1 && vx0) ? 1.f : 0.f));
            wwd[pix][3] = dup2(fy * fx                 * ((vy1 && vx1) ? 1.f : 0.f));
            const int yc0 = min(max(y0, 0), 63), yc1 = min(max(y0 + 1, 0), 63);
            const int xc0 = min(max(x0, 0), 63), xc1 = min(max(x0 + 1, 0), 63);
            const int t0y = yc0 - oy, t1y = yc1 - oy;
            const int t0x = xc0 - ox, t1x = xc1 - ox;
            const bool win = (t0y >= 0) && (t1y < SH) && (t0x >= 0) && (t1x < SW);
            inw[pix] = win;
            if (win) {
                cw[pix][0] = (t0y * SW + t0x) * PSTR; cw[pix][1] = (t0y * SW + t1x) * PSTR;
                cw[pix][2] = (t1y * SW + t0x) * PSTR; cw[pix][3] = (t1y * SW + t1x) * PSTR;
            } else {   // global pixel indices (rare path)
                cw[pix][0] = yc0 * 64 + xc0; cw[pix][1] = yc0 * 64 + xc1;
                cw[pix][2] = yc1 * 64 + xc0; cw[pix][3] = yc1 * 64 + xc1;
            }
        }
        const u64* web = swe + (k * 16) * 8;
        #pragma unroll
        for (int j = 0; j < 4; j++) {
            u64 vd[PPT][4];
            #pragma unroll
            for (int pix = 0; pix < PPT; pix++) {
                ulonglong2 A2, B2, C2, D2;
                if (inw[pix]) {
                    A2 = *reinterpret_cast<const ulonglong2*>(tile + cw[pix][0] + 4*j);
                    B2 = *reinterpret_cast<const ulonglong2*>(tile + cw[pix][1] + 4*j);
                    C2 = *reinterpret_cast<const ulonglong2*>(tile + cw[pix][2] + 4*j);
                    D2 = *reinterpret_cast<const ulonglong2*>(tile + cw[pix][3] + 4*j);
                } else {
                    const float* xq = xg + (size_t)(4*j) * HW;
                    const int i0 = cw[pix][0], i1 = cw[pix][1], i2 = cw[pix][2], i3 = cw[pix][3];
                    A2.x = pack2(xq[i0], xq[HW + i0]); A2.y = pack2(xq[2*HW + i0], xq[3*HW + i0]);
                    B2.x = pack2(xq[i1], xq[HW + i1]); B2.y = pack2(xq[2*HW + i1], xq[3*HW + i1]);
                    C2.x = pack2(xq[i2], xq[HW + i2]); C2.y = pack2(xq[2*HW + i2], xq[3*HW + i2]);
                    D2.x = pack2(xq[i3], xq[HW + i3]); D2.y = pack2(xq[2*HW + i3], xq[3*HW + i3]);
                }
                u64 v01 = mul2(wwd[pix][0], A2.x);
                ffma2(v01, wwd[pix][1], B2.x);
                ffma2(v01, wwd[pix][2], C2.x);
                ffma2(v01, wwd[pix][3], D2.x);
                u64 v23 = mul2(wwd[pix][0], A2.y);
                ffma2(v23, wwd[pix][1], B2.y);
                ffma2(v23, wwd[pix][2], C2.y);
                ffma2(v23, wwd[pix][3], D2.y);
                const float2 t01 = unpack2(v01), t23 = unpack2(v23);
                vd[pix][0] = dup2(t01.x); vd[pix][1] = dup2(t01.y);
                vd[pix][2] = dup2(t23.x); vd[pix][3] = dup2(t23.y);
            }
            #pragma unroll
            for (int q = 0; q < 4; q++) {
                const ulonglong2* we2 =
                    reinterpret_cast<const ulonglong2*>(web + (4*j + q) * 8);
                const ulonglong2 e0 = we2[0], e1 = we2[1], e2 = we2[2], e3 = we2[3];
                #pragma unroll
                for (int pix = 0; pix < PPT; pix++) {
                    const u64 v = vd[pix][q];
                    ffma2(acc[pix][0], e0.x, v); ffma2(acc[pix][1], e0.y, v);
                    ffma2(acc[pix][2], e1.x, v); ffma2(acc[pix][3], e1.y, v);
                    ffma2(acc[pix][4], e2.x, v); ffma2(acc[pix][5], e2.y, v);
                    ffma2(acc[pix][6], e3.x, v); ffma2(acc[pix][7], e3.y, v);
                }
            }
        }
    }
}

__global__ __launch_bounds__(THREADS) void fused_kernel(const float* __restrict__ x,
                                                        const float* __restrict__ w_off,
                                                        const float* __restrict__ b_off,
                                                        const float* __restrict__ w_dc) {
    extern __shared__ __align__(16) char smem_raw[];
    u64*   swc  = reinterpret_cast<u64*>(smem_raw);
    u64*   swe  = swc + SWC_U64;
    u64*   sb   = swe + SWE_U64;
    float* tile = reinterpret_cast<float*>(smem_raw + TILE_OFF);
    __shared__ float s_red[4][32];

    const int tid = threadIdx.x;
    const int bx = blockIdx.x, g = blockIdx.y, n = blockIdx.z;
    const int ty0 = (bx >> 2) * TH, tx0 = (bx & 3) * TW;
    const float* xg = x + ((size_t)(n * 64 + g * 16)) * HW;

    // Pack weights into smem (paired for f32x2)
    for (int i = tid; i < SWC_U64; i += THREADS) {
        const int slot = i % 12, c = (i / 12) % 16, pos = i / 192;
        int k = -1;
        if (slot < 5) k = slot;
        else if (slot >= 6 && slot <= 9) k = slot - 1;
        u64 v = 0ULL;
        if (k >= 0)
            v = pack2(w_off[((g*18 + 2*k)   * 16 + c) * 9 + pos],
                      w_off[((g*18 + 2*k+1) * 16 + c) * 9 + pos]);
        swc[i] = v;
    }
    for (int i = tid; i < SWE_U64; i += THREADS) {
        const int op = i % 8, c = (i / 8) % 16, k = i / 128;
        swe[i] = pack2(w_dc[((g*16 + 2*op)   * 16 + c) * 9 + k],
                       w_dc[((g*16 + 2*op+1) * 16 + c) * 9 + k]);
    }
    if (tid < SB_U64)
        sb[tid] = (tid < 9) ? pack2(b_off[g*18 + 2*tid], b_off[g*18 + 2*tid + 1]) : 0ULL;

    // Fill tile (zero halo outside image = conv boundary skip)
    for (int sp = tid; sp < SH * SW; sp += THREADS) {
        const int gy = ty0 - HALO + sp / SW;
        const int gx = tx0 - HALO + sp % SW;
        const bool in = ((unsigned)gy < 64u) && ((unsigned)gx < 64u);
        const int gp = gy * 64 + gx;
        #pragma unroll
        for (int c = 0; c < 16; c++)
            tile[sp * PSTR + c] = in ? xg[(size_t)c * HW + gp] : 0.f;
    }
    __syncthreads();

    const int r0loc = (tid >> 4) * PPT;     // 4 ADJACENT pixel rows per thread
    const int lanex = tid & 15;

    u64 acc[PPT][8];
    #pragma unroll
    for (int pix = 0; pix < PPT; pix++)
        #pragma unroll
        for (int op = 0; op < 8; op++) acc[pix][op] = 0ULL;

    chunk<0, 5>(acc, tile, xg, swc, swe, sb, r0loc, lanex, ty0, tx0);
    chunk<5, 4>(acc, tile, xg, swc, swe, sb, r0loc, lanex, ty0, tx0);

    // ---- write pre-norm output + block-local stats ----
    float sv[16], sq[16];
    #pragma unroll
    for (int o = 0; o < 16; o++) { sv[o] = 0.f; sq[o] = 0.f; }
    #pragma unroll
    for (int pix = 0; pix < PPT; pix++) {
        const int p0 = (ty0 + r0loc + pix) * 64 + tx0 + lanex;
        float* pre = g_pre + ((size_t)(n * 64 + g * 16)) * HW + p0;
        #pragma unroll
        for (int op = 0; op < 8; op++) {
            const float2 t = unpack2(acc[pix][op]);
            pre[(size_t)(2*op)     * HW] = t.x;
            pre[(size_t)(2*op + 1) * HW] = t.y;
            sv[2*op]     += t.x; sq[2*op]     += t.x * t.x;
            sv[2*op + 1] += t.y; sq[2*op + 1] += t.y * t.y;
        }
    }
    const int wi = tid >> 5, lane = tid & 31;
    #pragma unroll
    for (int o = 0; o < 16; o++) {
        #pragma unroll
        for (int d = 16; d; d >>= 1) {
            sv[o] += __shfl_xor_sync(0xffffffffu, sv[o], d);
            sq[o] += __shfl_xor_sync(0xffffffffu, sq[o], d);
        }
    }
    if (lane == 0) {
        #pragma unroll
        for (int o = 0; o < 16; o++) { s_red[wi][o] = sv[o]; s_red[wi][16 + o] = sq[o]; }
    }
    __syncthreads();
    if (tid < 32) {
        const float v = s_red[0][tid] + s_red[1][tid] + s_red[2][tid] + s_red[3][tid];
        g_part[(((n * 4 + g) * 8) + bx) * 32 + tid] = v;
    }
}

// Reduce 8 block-partials -> mean & rsqrt(var) per (n, oc)
__global__ void stats_kernel() {
    const int i = blockIdx.x * blockDim.x + threadIdx.x;   // (n*64 + oc)
    if (i >= N_ * 64) return;
    const int n = i >> 6, oc = i & 63;
    const int g = oc >> 4, o = oc & 15;
    float s = 0.f, q = 0.f;
    #pragma unroll
    for (int b = 0; b < 8; b++) {
        const float* pp = g_part + ((n * 4 + g) * 8 + b) * 32;
        s += pp[o]; q += pp[16 + o];
    }
    const float mean = s * (1.f / HW);
    const float var  = q * (1.f / HW) - mean * mean;
    g_stat[i]           = mean;
    g_stat[N_*64 + i]   = rsqrtf(var + 1e-5f);
}

// Normalize + exact GELU + transposed store
__global__ void norm_gelu_kernel(float* __restrict__ out) {
    const int oc = blockIdx.y;
    const int n  = blockIdx.z;

    const float mean = g_stat[n * 64 + oc];
    const float inv  = g_stat[N_*64 + n * 64 + oc];

    const int p4 = blockIdx.x * blockDim.x + threadIdx.x;
    const float4 v = reinterpret_cast<const float4*>(g_pre + ((size_t)(n * 64 + oc)) * HW)[p4];
    float4 r;
    { const float a = (v.x - mean) * inv; r.x = 0.5f * a * (1.f + erff(a * 0.7071067811865475f)); }
    { const float a = (v.y - mean) * inv; r.y = 0.5f * a * (1.f + erff(a * 0.7071067811865475f)); }
    { const float a = (v.z - mean) * inv; r.z = 0.5f * a * (1.f + erff(a * 0.7071067811865475f)); }
    { const float a = (v.w - mean) * inv; r.w = 0.5f * a * (1.f + erff(a * 0.7071067811865475f)); }

    const int b = n >> 3, d = n & 7;
    reinterpret_cast<float4*>(out + ((size_t)((b * 64 + oc) * 8 + d)) * HW)[p4] = r;
}

extern "C" void kernel_launch(void* const* d_in, const int* in_sizes, int n_in,
                              void* d_out, int out_size) {
    const float* x     = (const float*)d_in[0];
    const float* w_off = (const float*)d_in[1];
    const float* b_off = (const float*)d_in[2];
    const float* w_dc  = (const float*)d_in[3];
    // d_in[4] = b_dc: cancels exactly under per-channel mean subtraction.
    float* out = (float*)d_out;

    cudaFuncSetAttribute(fused_kernel,
                         cudaFuncAttributeMaxDynamicSharedMemorySize, SMEM_BYTES);

    touch_kernel<<<1, 32>>>();                                          // slot 0
    fused_kernel<<<dim3(8, G_, N_), THREADS, SMEM_BYTES>>>(x, w_off, b_off, w_dc);  // slot 1 (profiled)
    stats_kernel<<<2, 1024>>>();                                        // slot 2
    norm_gelu_kernel<<<dim3(HW / 1024, 64, N_), 256>>>(out);            // slot 3
}